// round 2
// baseline (speedup 1.0000x reference)
#include <cuda_runtime.h>
#include <cstdint>

#define Hh 576
#define Ww 640
#define HW (Hh*Ww)
#define BIGF 1e10f
#define EPSF 1e-5f

// ---- scratch (__device__ globals: no allocation allowed) ----
__device__ unsigned int g_depth_u[HW];   // z-buffer as uint bits (z>0 -> monotone order)
__device__ float        g_patchmin[HW];  // 5x5 patch min
__device__ float4       g_acc4[HW];      // color.xyz + imweights accumulator

__device__ __forceinline__ void red_add_v4(float4* p, float a, float b, float c, float d) {
    asm volatile("red.global.add.v4.f32 [%0], {%1,%2,%3,%4};"
                 :: "l"(__cvta_generic_to_global(p)),
                    "f"(a), "f"(b), "f"(c), "f"(d) : "memory");
}
__device__ __forceinline__ void red_add_f32(float* p, float v) {
    asm volatile("red.global.add.f32 [%0], %1;"
                 :: "l"(__cvta_generic_to_global(p)), "f"(v) : "memory");
}

// ---- k0: init z-buffer only (uint4 vectorized; HW % 4 == 0) ----
__global__ void k_init() {
    int i = blockIdx.x * blockDim.x + threadIdx.x;
    if (i >= HW / 4) return;
    uint4 v;
    v.x = v.y = v.z = v.w = __float_as_uint(BIGF);
    reinterpret_cast<uint4*>(g_depth_u)[i] = v;
}

// ---- k1: z-buffer scatter-min ----
__global__ void k_zmin(const float* __restrict__ pts, const int* __restrict__ mask, int n) {
    int i = blockIdx.x * blockDim.x + threadIdx.x;
    if (i >= n) return;
    float x = pts[3*i], y = pts[3*i+1], z = pts[3*i+2];
    int px = (int)floorf(x), py = (int)floorf(y);
    bool valid = (px >= 0) & (px < Ww) & (py >= 0) & (py < Hh) & (mask[i] > 0);
    if (valid)
        atomicMin(&g_depth_u[py * Ww + px], __float_as_uint(z));
}

// ---- k2: fused 5x5 patch-min via smem tile; also zeroes splat accumulators ----
// Block = 32x8 pixels, halo 2 each side -> smem tile 36x12.
#define TW 32
#define TH 8
#define SW (TW + 4)
#define SH (TH + 4)
__global__ void k_patchmin(float* __restrict__ out_weight) {
    __shared__ float tile[SH * SW];
    int tid = threadIdx.x;                      // 0..255
    int bx = blockIdx.x % (Ww / TW);            // 0..19
    int by = blockIdx.x / (Ww / TW);            // 0..71
    int x0 = bx * TW, y0 = by * TH;

    // cooperative halo load (SH*SW = 432 elems, 256 threads -> <=2 each)
    #pragma unroll
    for (int k = tid; k < SH * SW; k += 256) {
        int ly = k / SW, lx = k % SW;
        int gy = y0 + ly - 2, gx = x0 + lx - 2;
        float v = BIGF;
        if (gy >= 0 && gy < Hh && gx >= 0 && gx < Ww)
            v = __uint_as_float(g_depth_u[gy * Ww + gx]);
        tile[k] = v;
    }
    __syncthreads();

    int tx = tid % TW, ty = tid / TW;
    float m = BIGF;
    #pragma unroll
    for (int dy = 0; dy < 5; ++dy) {
        #pragma unroll
        for (int dx = 0; dx < 5; ++dx)
            m = fminf(m, tile[(ty + dy) * SW + (tx + dx)]);
    }
    int gi = (y0 + ty) * Ww + (x0 + tx);
    g_patchmin[gi] = m;
    // zero the splat accumulators (must happen before k_splat; this kernel does)
    g_acc4[gi] = make_float4(0.f, 0.f, 0.f, 0.f);
    out_weight[gi] = 0.f;
}

// ---- k3: visibility + 7x7 splat ----
__global__ void k_splat(const float* __restrict__ pts,
                        const float* __restrict__ color,
                        const float* __restrict__ imw,
                        const int*   __restrict__ mask,
                        const float* __restrict__ thresh,
                        float* __restrict__ out_weight,
                        float* __restrict__ out_vis,
                        int n) {
    int i = blockIdx.x * blockDim.x + threadIdx.x;
    if (i >= n) return;
    float x = pts[3*i], y = pts[3*i+1], z = pts[3*i+2];
    int px = (int)floorf(x), py = (int)floorf(y);
    bool valid = (px >= 0) & (px < Ww) & (py >= 0) & (py < Hh) & (mask[i] > 0);
    int cx = min(max(px, 0), Ww - 1);
    int cy = min(max(py, 0), Hh - 1);
    float pm = g_patchmin[cy * Ww + cx];
    float th = __ldg(thresh);
    bool vis = valid && (z <= pm + th);
    out_vis[i] = vis ? 1.0f : 0.0f;
    if (!vis) return;

    float c0 = color[3*i], c1 = color[3*i+1], c2 = color[3*i+2];
    float iw = imw[i];

    #pragma unroll
    for (int oy = -3; oy <= 3; ++oy) {
        int sy = py + oy;
        if (sy < 0 || sy >= Hh) continue;
        float dy = (float)sy + 0.5f - y;
        float dy2 = dy * dy + EPSF;
        #pragma unroll
        for (int ox = -3; ox <= 3; ++ox) {
            int sx = px + ox;
            if (sx < 0 || sx >= Ww) continue;
            float dx = (float)sx + 0.5f - x;
            float w = 1.0f / fmaf(dx, dx, dy2);
            int idx = sy * Ww + sx;
            red_add_v4(&g_acc4[idx], w * c0, w * c1, w * c2, w * iw);
            red_add_f32(&out_weight[idx], w);
        }
    }
}

// ---- k4: finalize, 4 pixels per thread, fully vectorized ----
__global__ void k_final(float* __restrict__ out_depth,
                        float* __restrict__ out_color,
                        float* __restrict__ out_imw) {
    int i = blockIdx.x * blockDim.x + threadIdx.x;
    if (i >= HW / 4) return;
    uint4 du = reinterpret_cast<const uint4*>(g_depth_u)[i];
    float4 dv;
    dv.x = (__uint_as_float(du.x) >= BIGF) ? 0.f : __uint_as_float(du.x);
    dv.y = (__uint_as_float(du.y) >= BIGF) ? 0.f : __uint_as_float(du.y);
    dv.z = (__uint_as_float(du.z) >= BIGF) ? 0.f : __uint_as_float(du.z);
    dv.w = (__uint_as_float(du.w) >= BIGF) ? 0.f : __uint_as_float(du.w);
    reinterpret_cast<float4*>(out_depth)[i] = dv;

    float4 a0 = g_acc4[4*i+0];
    float4 a1 = g_acc4[4*i+1];
    float4 a2 = g_acc4[4*i+2];
    float4 a3 = g_acc4[4*i+3];
    // color: 12 contiguous floats -> 3 float4 stores (out_color is 16B aligned)
    float4* oc = reinterpret_cast<float4*>(out_color + 12 * i);
    oc[0] = make_float4(a0.x, a0.y, a0.z, a1.x);
    oc[1] = make_float4(a1.y, a1.z, a2.x, a2.y);
    oc[2] = make_float4(a2.z, a3.x, a3.y, a3.z);
    reinterpret_cast<float4*>(out_imw)[i] = make_float4(a0.w, a1.w, a2.w, a3.w);
}

extern "C" void kernel_launch(void* const* d_in, const int* in_sizes, int n_in,
                              void* d_out, int out_size) {
    const float* pts    = (const float*)d_in[0];   // [1,N,3]
    const float* color  = (const float*)d_in[1];   // [1,N,3]
    const float* imw    = (const float*)d_in[2];   // [1,N,1]
    const int*   mask   = (const int*)  d_in[3];   // [1,N]
    const float* thresh = (const float*)d_in[4];   // [1]
    int n = in_sizes[3];                           // N = 200000

    float* out = (float*)d_out;
    float* out_depth  = out;            // [H,W]
    float* out_color  = out + HW;       // [H,W,3]
    float* out_imw    = out + HW * 4;   // [H,W,1]
    float* out_weight = out + HW * 5;   // [H,W]
    float* out_vis    = out + HW * 6;   // [N]

    const int BT = 256;
    int gp  = (n + BT - 1) / BT;
    int gi4 = (HW / 4 + BT - 1) / BT;
    int gt  = (Ww / TW) * (Hh / TH);    // 20 * 72 = 1440

    k_init<<<gi4, BT>>>();
    k_zmin<<<gp, BT>>>(pts, mask, n);
    k_patchmin<<<gt, BT>>>(out_weight);
    k_splat<<<gp, BT>>>(pts, color, imw, mask, thresh, out_weight, out_vis, n);
    k_final<<<gi4, BT>>>(out_depth, out_color, out_imw);
}

// round 3
// speedup vs baseline: 1.2667x; 1.2667x over previous
#include <cuda_runtime.h>
#include <cstdint>

#define Hh 576
#define Ww 640
#define HW (Hh*Ww)
#define BIGF 1e10f
#define EPSF 1e-5f

// ---- scratch (__device__ globals: no allocation allowed) ----
__device__ unsigned int g_depth_u[HW];   // z-buffer as uint bits (z>0 -> monotone order)
__device__ float        g_patchmin[HW];  // 5x5 patch min
__device__ float4       g_acc4[HW];      // color.xyz + imweights accumulator

__device__ __forceinline__ void red_add_v4(float4* p, float a, float b, float c, float d) {
    asm volatile("red.global.add.v4.f32 [%0], {%1,%2,%3,%4};"
                 :: "l"(__cvta_generic_to_global(p)),
                    "f"(a), "f"(b), "f"(c), "f"(d) : "memory");
}
__device__ __forceinline__ void red_add_f32(float* p, float v) {
    asm volatile("red.global.add.f32 [%0], %1;"
                 :: "l"(__cvta_generic_to_global(p)), "f"(v) : "memory");
}

// ---- k0: init z-buffer (uint4 vectorized; HW % 4 == 0) ----
__global__ void k_init() {
    int i = blockIdx.x * blockDim.x + threadIdx.x;
    if (i >= HW / 4) return;
    uint4 v;
    v.x = v.y = v.z = v.w = __float_as_uint(BIGF);
    reinterpret_cast<uint4*>(g_depth_u)[i] = v;
}

// ---- k1: z-buffer scatter-min ----
__global__ void k_zmin(const float* __restrict__ pts, const int* __restrict__ mask, int n) {
    int i = blockIdx.x * blockDim.x + threadIdx.x;
    if (i >= n) return;
    float x = pts[3*i], y = pts[3*i+1], z = pts[3*i+2];
    int px = __float2int_rd(x), py = __float2int_rd(y);
    bool valid = (px >= 0) & (px < Ww) & (py >= 0) & (py < Hh) & (mask[i] > 0);
    if (valid)
        atomicMin(&g_depth_u[py * Ww + px], __float_as_uint(z));
}

// ---- k2: fused 5x5 patch-min via smem tile; also zeroes splat accumulators ----
#define TW 32
#define TH 8
#define SW (TW + 4)
#define SH (TH + 4)
__global__ void k_patchmin(float* __restrict__ out_weight) {
    __shared__ float tile[SH * SW];
    int tid = threadIdx.x;
    int bx = blockIdx.x % (Ww / TW);
    int by = blockIdx.x / (Ww / TW);
    int x0 = bx * TW, y0 = by * TH;

    #pragma unroll
    for (int k = tid; k < SH * SW; k += 256) {
        int ly = k / SW, lx = k % SW;
        int gy = y0 + ly - 2, gx = x0 + lx - 2;
        float v = BIGF;
        if (gy >= 0 && gy < Hh && gx >= 0 && gx < Ww)
            v = __uint_as_float(g_depth_u[gy * Ww + gx]);
        tile[k] = v;
    }
    __syncthreads();

    int tx = tid % TW, ty = tid / TW;
    float m = BIGF;
    #pragma unroll
    for (int dy = 0; dy < 5; ++dy) {
        #pragma unroll
        for (int dx = 0; dx < 5; ++dx)
            m = fminf(m, tile[(ty + dy) * SW + (tx + dx)]);
    }
    int gi = (y0 + ty) * Ww + (x0 + tx);
    g_patchmin[gi] = m;
    g_acc4[gi] = make_float4(0.f, 0.f, 0.f, 0.f);
    out_weight[gi] = 0.f;
}

// ---- k3: visibility + warp-cooperative 7x7 splat ----
__global__ void k_splat(const float* __restrict__ pts,
                        const float* __restrict__ color,
                        const float* __restrict__ imw,
                        const int*   __restrict__ mask,
                        const float* __restrict__ thresh,
                        float* __restrict__ out_weight,
                        float* __restrict__ out_vis,
                        int n) {
    int i = blockIdx.x * blockDim.x + threadIdx.x;
    int lane = threadIdx.x & 31;

    // per-lane constant splat offsets: update u covers (oy,ox) = (u/7-3, u%7-3)
    int u0 = lane, u1 = lane + 32;
    int ox0 = u0 % 7 - 3, oy0 = u0 / 7 - 3;
    int ox1 = u1 % 7 - 3, oy1 = u1 / 7 - 3;
    float cx0 = (float)ox0 + 0.5f, cy0 = (float)oy0 + 0.5f;
    float cx1 = (float)ox1 + 0.5f, cy1 = (float)oy1 + 0.5f;
    bool has1 = (u1 < 49);

    bool vis = false;
    float x = 0.f, y = 0.f, c0 = 0.f, c1 = 0.f, c2 = 0.f, iw = 0.f;
    int px = 0, py = 0;

    if (i < n) {
        x = pts[3*i]; y = pts[3*i+1];
        float z = pts[3*i+2];
        px = __float2int_rd(x); py = __float2int_rd(y);
        bool valid = (px >= 0) & (px < Ww) & (py >= 0) & (py < Hh) & (mask[i] > 0);
        int ccx = min(max(px, 0), Ww - 1);
        int ccy = min(max(py, 0), Hh - 1);
        float pm = g_patchmin[ccy * Ww + ccx];
        float th = __ldg(thresh);
        vis = valid && (z <= pm + th);
        out_vis[i] = vis ? 1.0f : 0.0f;
        if (vis) {
            c0 = color[3*i]; c1 = color[3*i+1]; c2 = color[3*i+2];
            iw = imw[i];
        }
    }

    unsigned vm = __ballot_sync(0xffffffffu, vis);
    while (vm) {
        int src = __ffs(vm) - 1;
        vm &= vm - 1;
        float xx  = __shfl_sync(0xffffffffu, x,  src);
        float yy  = __shfl_sync(0xffffffffu, y,  src);
        float s0  = __shfl_sync(0xffffffffu, c0, src);
        float s1  = __shfl_sync(0xffffffffu, c1, src);
        float s2  = __shfl_sync(0xffffffffu, c2, src);
        float sw  = __shfl_sync(0xffffffffu, iw, src);
        int   pxb = __shfl_sync(0xffffffffu, px, src);
        int   pyb = __shfl_sync(0xffffffffu, py, src);
        float fx  = (float)pxb - xx;   // dx = fx + cx
        float fy  = (float)pyb - yy;

        // round 0: update index u = lane (0..31)
        {
            int sx = pxb + ox0, sy = pyb + oy0;
            if (((unsigned)sx < Ww) & ((unsigned)sy < Hh)) {
                float dx = fx + cx0;
                float dy = fy + cy0;
                float w = __fdividef(1.0f, fmaf(dx, dx, fmaf(dy, dy, EPSF)));
                int idx = sy * Ww + sx;
                red_add_v4(&g_acc4[idx], w * s0, w * s1, w * s2, w * sw);
                red_add_f32(&out_weight[idx], w);
            }
        }
        // round 1: u = lane + 32 (lanes 0..16)
        if (has1) {
            int sx = pxb + ox1, sy = pyb + oy1;
            if (((unsigned)sx < Ww) & ((unsigned)sy < Hh)) {
                float dx = fx + cx1;
                float dy = fy + cy1;
                float w = __fdividef(1.0f, fmaf(dx, dx, fmaf(dy, dy, EPSF)));
                int idx = sy * Ww + sx;
                red_add_v4(&g_acc4[idx], w * s0, w * s1, w * s2, w * sw);
                red_add_f32(&out_weight[idx], w);
            }
        }
    }
}

// ---- k4: finalize, 4 pixels per thread, fully vectorized ----
__global__ void k_final(float* __restrict__ out_depth,
                        float* __restrict__ out_color,
                        float* __restrict__ out_imw) {
    int i = blockIdx.x * blockDim.x + threadIdx.x;
    if (i >= HW / 4) return;
    uint4 du = reinterpret_cast<const uint4*>(g_depth_u)[i];
    float4 dv;
    dv.x = (__uint_as_float(du.x) >= BIGF) ? 0.f : __uint_as_float(du.x);
    dv.y = (__uint_as_float(du.y) >= BIGF) ? 0.f : __uint_as_float(du.y);
    dv.z = (__uint_as_float(du.z) >= BIGF) ? 0.f : __uint_as_float(du.z);
    dv.w = (__uint_as_float(du.w) >= BIGF) ? 0.f : __uint_as_float(du.w);
    reinterpret_cast<float4*>(out_depth)[i] = dv;

    float4 a0 = g_acc4[4*i+0];
    float4 a1 = g_acc4[4*i+1];
    float4 a2 = g_acc4[4*i+2];
    float4 a3 = g_acc4[4*i+3];
    float4* oc = reinterpret_cast<float4*>(out_color + 12 * i);
    oc[0] = make_float4(a0.x, a0.y, a0.z, a1.x);
    oc[1] = make_float4(a1.y, a1.z, a2.x, a2.y);
    oc[2] = make_float4(a2.z, a3.x, a3.y, a3.z);
    reinterpret_cast<float4*>(out_imw)[i] = make_float4(a0.w, a1.w, a2.w, a3.w);
}

extern "C" void kernel_launch(void* const* d_in, const int* in_sizes, int n_in,
                              void* d_out, int out_size) {
    const float* pts    = (const float*)d_in[0];
    const float* color  = (const float*)d_in[1];
    const float* imw    = (const float*)d_in[2];
    const int*   mask   = (const int*)  d_in[3];
    const float* thresh = (const float*)d_in[4];
    int n = in_sizes[3];

    float* out = (float*)d_out;
    float* out_depth  = out;
    float* out_color  = out + HW;
    float* out_imw    = out + HW * 4;
    float* out_weight = out + HW * 5;
    float* out_vis    = out + HW * 6;

    const int BT = 256;
    int gp  = (n + BT - 1) / BT;
    int gi4 = (HW / 4 + BT - 1) / BT;
    int gt  = (Ww / TW) * (Hh / TH);

    k_init<<<gi4, BT>>>();
    k_zmin<<<gp, BT>>>(pts, mask, n);
    k_patchmin<<<gt, BT>>>(out_weight);
    k_splat<<<gp, BT>>>(pts, color, imw, mask, thresh, out_weight, out_vis, n);
    k_final<<<gi4, BT>>>(out_depth, out_color, out_imw);
}

// round 4
// speedup vs baseline: 1.3735x; 1.0843x over previous
#include <cuda_runtime.h>
#include <cstdint>

#define Hh 576
#define Ww 640
#define HW (Hh*Ww)
#define BIGF 1e10f
#define EPSF 1e-5f

// ---- scratch (__device__ globals; zero-initialized at module load) ----
// Depth z-buffer stored as COMPLEMENT keys: key = ~__float_as_uint(z).
// z > 0  =>  key in (0x80000000, 0xFFFFFFFF), so key == 0 means "empty".
// min(z) == decode(max(key)); atomicMax with implicit 0 init works.
// k_final restores keys to 0, so every execution leaves the buffer reset.
__device__ unsigned int g_depth_key[HW];
__device__ float        g_patchmin[HW];
__device__ float4       g_acc4[HW];

__device__ __forceinline__ void red_add_v4(float4* p, float a, float b, float c, float d) {
    asm volatile("red.global.add.v4.f32 [%0], {%1,%2,%3,%4};"
                 :: "l"(__cvta_generic_to_global(p)),
                    "f"(a), "f"(b), "f"(c), "f"(d) : "memory");
}
__device__ __forceinline__ void red_add_f32(float* p, float v) {
    asm volatile("red.global.add.f32 [%0], %1;"
                 :: "l"(__cvta_generic_to_global(p)), "f"(v) : "memory");
}

// ---- k1: z-buffer scatter-min (as complement-key atomicMax), 4 pts/thread ----
__global__ void k_zmin(const float* __restrict__ pts, const int* __restrict__ mask, int n4) {
    int i4 = blockIdx.x * blockDim.x + threadIdx.x;
    if (i4 >= n4) return;
    const float4* p4 = reinterpret_cast<const float4*>(pts) + 3 * i4;
    float4 a = p4[0], b = p4[1], c = p4[2];
    int4 mk = reinterpret_cast<const int4*>(mask)[i4];
    // points: (a.x,a.y,a.z) (a.w,b.x,b.y) (b.z,b.w,c.x) (c.y,c.z,c.w)
    float X[4] = {a.x, a.w, b.z, c.y};
    float Y[4] = {a.y, b.x, b.w, c.z};
    float Z[4] = {a.z, b.y, c.x, c.w};
    int   M[4] = {mk.x, mk.y, mk.z, mk.w};
    #pragma unroll
    for (int k = 0; k < 4; ++k) {
        int px = __float2int_rd(X[k]), py = __float2int_rd(Y[k]);
        bool valid = (px >= 0) & (px < Ww) & (py >= 0) & (py < Hh) & (M[k] > 0);
        if (valid)
            atomicMax(&g_depth_key[py * Ww + px], ~__float_as_uint(Z[k]));
    }
}

// ---- k2: fused 5x5 patch-min via smem key-max tile; zeroes splat accumulators ----
#define TW 32
#define TH 8
#define SW (TW + 4)
#define SH (TH + 4)
__global__ void k_patchmin(float* __restrict__ out_weight) {
    __shared__ unsigned int tile[SH * SW];
    int tid = threadIdx.x;
    int bx = blockIdx.x % (Ww / TW);
    int by = blockIdx.x / (Ww / TW);
    int x0 = bx * TW, y0 = by * TH;

    #pragma unroll
    for (int k = tid; k < SH * SW; k += 256) {
        int ly = k / SW, lx = k % SW;
        int gy = y0 + ly - 2, gx = x0 + lx - 2;
        unsigned v = 0u;  // empty (BIG depth)
        if (gy >= 0 && gy < Hh && gx >= 0 && gx < Ww)
            v = g_depth_key[gy * Ww + gx];
        tile[k] = v;
    }
    __syncthreads();

    int tx = tid % TW, ty = tid / TW;
    unsigned m = 0u;
    #pragma unroll
    for (int dy = 0; dy < 5; ++dy) {
        #pragma unroll
        for (int dx = 0; dx < 5; ++dx)
            m = max(m, tile[(ty + dy) * SW + (tx + dx)]);
    }
    int gi = (y0 + ty) * Ww + (x0 + tx);
    g_patchmin[gi] = (m == 0u) ? BIGF : __uint_as_float(~m);
    g_acc4[gi] = make_float4(0.f, 0.f, 0.f, 0.f);
    out_weight[gi] = 0.f;
}

// ---- k3: visibility + warp-cooperative 7x7 splat (uniform-load broadcast) ----
__global__ void __launch_bounds__(256) k_splat(
                        const float* __restrict__ pts,
                        const float* __restrict__ color,
                        const float* __restrict__ imw,
                        const int*   __restrict__ mask,
                        const float* __restrict__ thresh,
                        float* __restrict__ out_weight,
                        float* __restrict__ out_vis,
                        int n) {
    int i = blockIdx.x * blockDim.x + threadIdx.x;
    int lane = threadIdx.x & 31;
    int warp_base = i - lane;

    // per-lane constant splat offsets: update u covers (oy,ox) = (u/7-3, u%7-3)
    int u1 = lane + 32;
    int ox0 = lane % 7 - 3, oy0 = lane / 7 - 3;
    int ox1 = u1 % 7 - 3,   oy1 = u1 / 7 - 3;
    float cxo0 = (float)ox0 + 0.5f, cyo0 = (float)oy0 + 0.5f;
    float cxo1 = (float)ox1 + 0.5f, cyo1 = (float)oy1 + 0.5f;
    int ioff0 = oy0 * Ww + ox0;
    int ioff1 = oy1 * Ww + ox1;
    bool has1 = (u1 < 49);

    bool vis = false;
    if (i < n) {
        float x = pts[3*i], y = pts[3*i+1], z = pts[3*i+2];
        int px = __float2int_rd(x), py = __float2int_rd(y);
        bool valid = (px >= 0) & (px < Ww) & (py >= 0) & (py < Hh) & (mask[i] > 0);
        int ccx = min(max(px, 0), Ww - 1);
        int ccy = min(max(py, 0), Hh - 1);
        float pm = g_patchmin[ccy * Ww + ccx];
        float th = __ldg(thresh);
        vis = valid && (z <= pm + th);
        out_vis[i] = vis ? 1.0f : 0.0f;
    }

    unsigned vm = __ballot_sync(0xffffffffu, vis);
    while (vm) {
        int src = __ffs(vm) - 1;
        vm &= vm - 1;
        int j = warp_base + src;              // warp-uniform -> broadcast loads
        float xx = __ldg(&pts[3*j]);
        float yy = __ldg(&pts[3*j+1]);
        float s0 = __ldg(&color[3*j]);
        float s1 = __ldg(&color[3*j+1]);
        float s2 = __ldg(&color[3*j+2]);
        float sw = __ldg(&imw[j]);
        int pxb = __float2int_rd(xx);
        int pyb = __float2int_rd(yy);
        float fx = (float)pxb - xx;           // dx = fx + cxo
        float fy = (float)pyb - yy;
        int base = pyb * Ww + pxb;

        // round 0: update u = lane (0..31)
        {
            int sx = pxb + ox0, sy = pyb + oy0;
            if (((unsigned)sx < Ww) & ((unsigned)sy < Hh)) {
                float dx = fx + cxo0;
                float dy = fy + cyo0;
                float w = __fdividef(1.0f, fmaf(dx, dx, fmaf(dy, dy, EPSF)));
                int idx = base + ioff0;
                red_add_v4(&g_acc4[idx], w * s0, w * s1, w * s2, w * sw);
                red_add_f32(&out_weight[idx], w);
            }
        }
        // round 1: u = lane + 32 (lanes 0..16)
        if (has1) {
            int sx = pxb + ox1, sy = pyb + oy1;
            if (((unsigned)sx < Ww) & ((unsigned)sy < Hh)) {
                float dx = fx + cxo1;
                float dy = fy + cyo1;
                float w = __fdividef(1.0f, fmaf(dx, dx, fmaf(dy, dy, EPSF)));
                int idx = base + ioff1;
                red_add_v4(&g_acc4[idx], w * s0, w * s1, w * s2, w * sw);
                red_add_f32(&out_weight[idx], w);
            }
        }
    }
}

// ---- k4: finalize (vectorized) + self-restore depth keys to 0 ----
__global__ void k_final(float* __restrict__ out_depth,
                        float* __restrict__ out_color,
                        float* __restrict__ out_imw) {
    int i = blockIdx.x * blockDim.x + threadIdx.x;
    if (i >= HW / 4) return;
    uint4 ku = reinterpret_cast<const uint4*>(g_depth_key)[i];
    float4 dv;
    dv.x = ku.x ? __uint_as_float(~ku.x) : 0.f;
    dv.y = ku.y ? __uint_as_float(~ku.y) : 0.f;
    dv.z = ku.z ? __uint_as_float(~ku.z) : 0.f;
    dv.w = ku.w ? __uint_as_float(~ku.w) : 0.f;
    reinterpret_cast<float4*>(out_depth)[i] = dv;
    reinterpret_cast<uint4*>(g_depth_key)[i] = make_uint4(0u, 0u, 0u, 0u);

    float4 a0 = g_acc4[4*i+0];
    float4 a1 = g_acc4[4*i+1];
    float4 a2 = g_acc4[4*i+2];
    float4 a3 = g_acc4[4*i+3];
    float4* oc = reinterpret_cast<float4*>(out_color + 12 * i);
    oc[0] = make_float4(a0.x, a0.y, a0.z, a1.x);
    oc[1] = make_float4(a1.y, a1.z, a2.x, a2.y);
    oc[2] = make_float4(a2.z, a3.x, a3.y, a3.z);
    reinterpret_cast<float4*>(out_imw)[i] = make_float4(a0.w, a1.w, a2.w, a3.w);
}

// scalar tail for n % 4 != 0 (not hit for N=200000, kept for safety)
__global__ void k_zmin_tail(const float* __restrict__ pts, const int* __restrict__ mask,
                            int start, int n) {
    int i = start + blockIdx.x * blockDim.x + threadIdx.x;
    if (i >= n) return;
    float x = pts[3*i], y = pts[3*i+1], z = pts[3*i+2];
    int px = __float2int_rd(x), py = __float2int_rd(y);
    bool valid = (px >= 0) & (px < Ww) & (py >= 0) & (py < Hh) & (mask[i] > 0);
    if (valid)
        atomicMax(&g_depth_key[py * Ww + px], ~__float_as_uint(z));
}

extern "C" void kernel_launch(void* const* d_in, const int* in_sizes, int n_in,
                              void* d_out, int out_size) {
    const float* pts    = (const float*)d_in[0];
    const float* color  = (const float*)d_in[1];
    const float* imw    = (const float*)d_in[2];
    const int*   mask   = (const int*)  d_in[3];
    const float* thresh = (const float*)d_in[4];
    int n = in_sizes[3];
    int n4 = n / 4;

    float* out = (float*)d_out;
    float* out_depth  = out;
    float* out_color  = out + HW;
    float* out_imw    = out + HW * 4;
    float* out_weight = out + HW * 5;
    float* out_vis    = out + HW * 6;

    const int BT = 256;
    int gz  = (n4 + BT - 1) / BT;
    int gp  = (n + BT - 1) / BT;
    int gi4 = (HW / 4 + BT - 1) / BT;
    int gt  = (Ww / TW) * (Hh / TH);

    k_zmin<<<gz, BT>>>(pts, mask, n4);
    if (n % 4) k_zmin_tail<<<1, BT>>>(pts, mask, n4 * 4, n);
    k_patchmin<<<gt, BT>>>(out_weight);
    k_splat<<<gp, BT>>>(pts, color, imw, mask, thresh, out_weight, out_vis, n);
    k_final<<<gi4, BT>>>(out_depth, out_color, out_imw);
}

// round 5
// speedup vs baseline: 1.5379x; 1.1197x over previous
#include <cuda_runtime.h>
#include <cstdint>

#define Hh 576
#define Ww 640
#define HW (Hh*Ww)
#define BIGF 1e10f
#define EPSF 1e-5f

// ---- scratch (__device__ globals; zero-initialized at module load) ----
// Depth z-buffer stored as COMPLEMENT keys: key = ~__float_as_uint(z).
// z > 0  =>  key in (0x80000000, 0xFFFFFFFF), so key == 0 means "empty".
// min(z) == decode(max(key)); atomicMax with implicit 0 init works.
// k_final restores keys to 0, so every execution leaves the buffer reset.
__device__ unsigned int g_depth_key[HW];
__device__ float        g_patchmin[HW];
__device__ float4       g_acc4[HW];

__device__ __forceinline__ void red_add_v4(float4* p, float a, float b, float c, float d) {
    asm volatile("red.global.add.v4.f32 [%0], {%1,%2,%3,%4};"
                 :: "l"(__cvta_generic_to_global(p)),
                    "f"(a), "f"(b), "f"(c), "f"(d) : "memory");
}
__device__ __forceinline__ void red_add_f32(float* p, float v) {
    asm volatile("red.global.add.f32 [%0], %1;"
                 :: "l"(__cvta_generic_to_global(p)), "f"(v) : "memory");
}

// ---- k1: z-buffer scatter-min (complement-key atomicMax), 1 pt/thread ----
__global__ void k_zmin(const float* __restrict__ pts, const int* __restrict__ mask, int n) {
    int i = blockIdx.x * blockDim.x + threadIdx.x;
    if (i >= n) return;
    float x = __ldg(&pts[3*i]), y = __ldg(&pts[3*i+1]), z = __ldg(&pts[3*i+2]);
    int px = __float2int_rd(x), py = __float2int_rd(y);
    bool valid = (px >= 0) & (px < Ww) & (py >= 0) & (py < Hh) & (mask[i] > 0);
    if (valid)
        atomicMax(&g_depth_key[py * Ww + px], ~__float_as_uint(z));
}

// ---- k2: fused 5x5 patch-min via smem key-max tile; zeroes splat accumulators ----
#define TW 32
#define TH 8
#define SW (TW + 4)
#define SH (TH + 4)
__global__ void k_patchmin(float* __restrict__ out_weight) {
    __shared__ unsigned int tile[SH * SW];
    int tid = threadIdx.x;
    int bx = blockIdx.x % (Ww / TW);
    int by = blockIdx.x / (Ww / TW);
    int x0 = bx * TW, y0 = by * TH;

    #pragma unroll
    for (int k = tid; k < SH * SW; k += 256) {
        int ly = k / SW, lx = k % SW;
        int gy = y0 + ly - 2, gx = x0 + lx - 2;
        unsigned v = 0u;  // empty (BIG depth)
        if (gy >= 0 && gy < Hh && gx >= 0 && gx < Ww)
            v = g_depth_key[gy * Ww + gx];
        tile[k] = v;
    }
    __syncthreads();

    int tx = tid % TW, ty = tid / TW;
    unsigned m = 0u;
    #pragma unroll
    for (int dy = 0; dy < 5; ++dy) {
        #pragma unroll
        for (int dx = 0; dx < 5; ++dx)
            m = max(m, tile[(ty + dy) * SW + (tx + dx)]);
    }
    int gi = (y0 + ty) * Ww + (x0 + tx);
    g_patchmin[gi] = (m == 0u) ? BIGF : __uint_as_float(~m);
    g_acc4[gi] = make_float4(0.f, 0.f, 0.f, 0.f);
    out_weight[gi] = 0.f;
}

// ---- k3: visibility + warp-cooperative 7x7 splat (uniform-load broadcast) ----
__global__ void __launch_bounds__(256) k_splat(
                        const float* __restrict__ pts,
                        const float* __restrict__ color,
                        const float* __restrict__ imw,
                        const int*   __restrict__ mask,
                        const float* __restrict__ thresh,
                        float* __restrict__ out_weight,
                        float* __restrict__ out_vis,
                        int n) {
    int i = blockIdx.x * blockDim.x + threadIdx.x;
    int lane = threadIdx.x & 31;
    int warp_base = i - lane;

    // per-lane constant splat offsets: update u covers (oy,ox) = (u/7-3, u%7-3)
    int u1 = lane + 32;
    int ox0 = lane % 7 - 3, oy0 = lane / 7 - 3;
    int ox1 = u1 % 7 - 3,   oy1 = u1 / 7 - 3;
    float cxo0 = (float)ox0 + 0.5f, cyo0 = (float)oy0 + 0.5f;
    float cxo1 = (float)ox1 + 0.5f, cyo1 = (float)oy1 + 0.5f;
    int ioff0 = oy0 * Ww + ox0;
    int ioff1 = oy1 * Ww + ox1;
    bool has1 = (u1 < 49);

    bool vis = false;
    if (i < n) {
        float x = pts[3*i], y = pts[3*i+1], z = pts[3*i+2];
        int px = __float2int_rd(x), py = __float2int_rd(y);
        bool valid = (px >= 0) & (px < Ww) & (py >= 0) & (py < Hh) & (mask[i] > 0);
        int ccx = min(max(px, 0), Ww - 1);
        int ccy = min(max(py, 0), Hh - 1);
        float pm = g_patchmin[ccy * Ww + ccx];
        float th = __ldg(thresh);
        vis = valid && (z <= pm + th);
        out_vis[i] = vis ? 1.0f : 0.0f;
    }

    unsigned vm = __ballot_sync(0xffffffffu, vis);
    while (vm) {
        int src = __ffs(vm) - 1;
        vm &= vm - 1;
        int j = warp_base + src;              // warp-uniform -> broadcast loads
        float xx = __ldg(&pts[3*j]);
        float yy = __ldg(&pts[3*j+1]);
        float s0 = __ldg(&color[3*j]);
        float s1 = __ldg(&color[3*j+1]);
        float s2 = __ldg(&color[3*j+2]);
        float sw = __ldg(&imw[j]);
        int pxb = __float2int_rd(xx);
        int pyb = __float2int_rd(yy);
        float fx = (float)pxb - xx;           // dx = fx + cxo
        float fy = (float)pyb - yy;
        int base = pyb * Ww + pxb;

        // round 0: update u = lane (0..31)
        {
            int sx = pxb + ox0, sy = pyb + oy0;
            if (((unsigned)sx < Ww) & ((unsigned)sy < Hh)) {
                float dx = fx + cxo0;
                float dy = fy + cyo0;
                float w = __fdividef(1.0f, fmaf(dx, dx, fmaf(dy, dy, EPSF)));
                int idx = base + ioff0;
                red_add_v4(&g_acc4[idx], w * s0, w * s1, w * s2, w * sw);
                red_add_f32(&out_weight[idx], w);
            }
        }
        // round 1: u = lane + 32 (lanes 0..16)
        if (has1) {
            int sx = pxb + ox1, sy = pyb + oy1;
            if (((unsigned)sx < Ww) & ((unsigned)sy < Hh)) {
                float dx = fx + cxo1;
                float dy = fy + cyo1;
                float w = __fdividef(1.0f, fmaf(dx, dx, fmaf(dy, dy, EPSF)));
                int idx = base + ioff1;
                red_add_v4(&g_acc4[idx], w * s0, w * s1, w * s2, w * sw);
                red_add_f32(&out_weight[idx], w);
            }
        }
    }
}

// ---- k4: finalize, 1 pixel/thread (max parallelism) + depth-key self-reset ----
__global__ void k_final(float* __restrict__ out_depth,
                        float* __restrict__ out_color,
                        float* __restrict__ out_imw) {
    int i = blockIdx.x * blockDim.x + threadIdx.x;
    if (i >= HW) return;
    unsigned k = g_depth_key[i];
    float4 a = g_acc4[i];
    out_depth[i] = k ? __uint_as_float(~k) : 0.f;
    g_depth_key[i] = 0u;
    out_color[3*i]   = a.x;
    out_color[3*i+1] = a.y;
    out_color[3*i+2] = a.z;
    out_imw[i] = a.w;
}

extern "C" void kernel_launch(void* const* d_in, const int* in_sizes, int n_in,
                              void* d_out, int out_size) {
    const float* pts    = (const float*)d_in[0];
    const float* color  = (const float*)d_in[1];
    const float* imw    = (const float*)d_in[2];
    const int*   mask   = (const int*)  d_in[3];
    const float* thresh = (const float*)d_in[4];
    int n = in_sizes[3];

    float* out = (float*)d_out;
    float* out_depth  = out;
    float* out_color  = out + HW;
    float* out_imw    = out + HW * 4;
    float* out_weight = out + HW * 5;
    float* out_vis    = out + HW * 6;

    const int BT = 256;
    int gp  = (n + BT - 1) / BT;          // 782
    int gf  = (HW + BT - 1) / BT;         // 1440
    int gt  = (Ww / TW) * (Hh / TH);      // 1440

    k_zmin<<<gp, BT>>>(pts, mask, n);
    k_patchmin<<<gt, BT>>>(out_weight);
    k_splat<<<gp, BT>>>(pts, color, imw, mask, thresh, out_weight, out_vis, n);
    k_final<<<gf, BT>>>(out_depth, out_color, out_imw);
}

// round 6
// speedup vs baseline: 1.5431x; 1.0034x over previous
#include <cuda_runtime.h>
#include <cstdint>

#define Hh 576
#define Ww 640
#define HW (Hh*Ww)
#define BIGF 1e10f
#define EPSF 1e-5f

// ---- scratch (__device__ globals; zero-initialized at module load) ----
// Depth z-buffer stored as COMPLEMENT keys: key = ~__float_as_uint(z).
// z > 0 => key in (0x80000000, 0xFFFFFFFF); key == 0 means "empty".
// min(z) == decode(max(key)); atomicMax with implicit 0 init works.
// k_final restores keys to 0 (pure stores), so every launch leaves state reset.
__device__ unsigned int g_depth_key[HW];
__device__ float        g_patchmin[HW];
__device__ float4       g_acc4[HW];

__device__ __forceinline__ void red_add_v4(float4* p, float a, float b, float c, float d) {
    asm volatile("red.global.add.v4.f32 [%0], {%1,%2,%3,%4};"
                 :: "l"(__cvta_generic_to_global(p)),
                    "f"(a), "f"(b), "f"(c), "f"(d) : "memory");
}
__device__ __forceinline__ void red_add_f32(float* p, float v) {
    asm volatile("red.global.add.f32 [%0], %1;"
                 :: "l"(__cvta_generic_to_global(p)), "f"(v) : "memory");
}

// ---- k1: z-buffer scatter-min (complement-key atomicMax), 1 pt/thread ----
__global__ void k_zmin(const float* __restrict__ pts, const int* __restrict__ mask, int n) {
    int i = blockIdx.x * blockDim.x + threadIdx.x;
    if (i >= n) return;
    float x = __ldg(&pts[3*i]), y = __ldg(&pts[3*i+1]), z = __ldg(&pts[3*i+2]);
    int px = __float2int_rd(x), py = __float2int_rd(y);
    bool valid = (px >= 0) & (px < Ww) & (py >= 0) & (py < Hh) & (mask[i] > 0);
    if (valid)
        atomicMax(&g_depth_key[py * Ww + px], ~__float_as_uint(z));
}

// ---- k2: 5x5 patch-min (smem key-max) + depth output + accumulator zeroing ----
#define TW 32
#define TH 8
#define SW (TW + 4)
#define SH (TH + 4)
__global__ void k_patchmin(float* __restrict__ out_weight,
                           float* __restrict__ out_depth) {
    __shared__ unsigned int tile[SH * SW];
    int tid = threadIdx.x;
    int bx = blockIdx.x % (Ww / TW);
    int by = blockIdx.x / (Ww / TW);
    int x0 = bx * TW, y0 = by * TH;

    #pragma unroll
    for (int k = tid; k < SH * SW; k += 256) {
        int ly = k / SW, lx = k % SW;
        int gy = y0 + ly - 2, gx = x0 + lx - 2;
        unsigned v = 0u;  // empty (BIG depth)
        if (gy >= 0 && gy < Hh && gx >= 0 && gx < Ww)
            v = g_depth_key[gy * Ww + gx];
        tile[k] = v;
    }
    __syncthreads();

    int tx = tid % TW, ty = tid / TW;
    unsigned m = 0u;
    #pragma unroll
    for (int dy = 0; dy < 5; ++dy) {
        #pragma unroll
        for (int dx = 0; dx < 5; ++dx)
            m = max(m, tile[(ty + dy) * SW + (tx + dx)]);
    }
    int gi = (y0 + ty) * Ww + (x0 + tx);
    g_patchmin[gi] = (m == 0u) ? BIGF : __uint_as_float(~m);

    // center key is already in the tile: emit final depth image here
    unsigned ck = tile[(ty + 2) * SW + (tx + 2)];
    out_depth[gi] = ck ? __uint_as_float(~ck) : 0.f;

    g_acc4[gi] = make_float4(0.f, 0.f, 0.f, 0.f);
    out_weight[gi] = 0.f;
}

// ---- k3: visibility + warp-cooperative 7x7 splat (uniform-load broadcast) ----
__global__ void __launch_bounds__(256) k_splat(
                        const float* __restrict__ pts,
                        const float* __restrict__ color,
                        const float* __restrict__ imw,
                        const int*   __restrict__ mask,
                        const float* __restrict__ thresh,
                        float* __restrict__ out_weight,
                        float* __restrict__ out_vis,
                        int n) {
    int i = blockIdx.x * blockDim.x + threadIdx.x;
    int lane = threadIdx.x & 31;
    int warp_base = i - lane;

    // per-lane constant splat offsets: update u covers (oy,ox) = (u/7-3, u%7-3)
    int u1 = lane + 32;
    int ox0 = lane % 7 - 3, oy0 = lane / 7 - 3;
    int ox1 = u1 % 7 - 3,   oy1 = u1 / 7 - 3;
    float cxo0 = (float)ox0 + 0.5f, cyo0 = (float)oy0 + 0.5f;
    float cxo1 = (float)ox1 + 0.5f, cyo1 = (float)oy1 + 0.5f;
    int ioff0 = oy0 * Ww + ox0;
    int ioff1 = oy1 * Ww + ox1;
    bool has1 = (u1 < 49);

    bool vis = false;
    if (i < n) {
        float x = pts[3*i], y = pts[3*i+1], z = pts[3*i+2];
        int px = __float2int_rd(x), py = __float2int_rd(y);
        bool valid = (px >= 0) & (px < Ww) & (py >= 0) & (py < Hh) & (mask[i] > 0);
        int ccx = min(max(px, 0), Ww - 1);
        int ccy = min(max(py, 0), Hh - 1);
        float pm = g_patchmin[ccy * Ww + ccx];
        float th = __ldg(thresh);
        vis = valid && (z <= pm + th);
        out_vis[i] = vis ? 1.0f : 0.0f;
    }

    unsigned vm = __ballot_sync(0xffffffffu, vis);
    while (vm) {
        int src = __ffs(vm) - 1;
        vm &= vm - 1;
        int j = warp_base + src;              // warp-uniform -> broadcast loads
        float xx = __ldg(&pts[3*j]);
        float yy = __ldg(&pts[3*j+1]);
        float s0 = __ldg(&color[3*j]);
        float s1 = __ldg(&color[3*j+1]);
        float s2 = __ldg(&color[3*j+2]);
        float sw = __ldg(&imw[j]);
        int pxb = __float2int_rd(xx);
        int pyb = __float2int_rd(yy);
        float fx = (float)pxb - xx;           // dx = fx + cxo
        float fy = (float)pyb - yy;
        int base = pyb * Ww + pxb;

        {
            int sx = pxb + ox0, sy = pyb + oy0;
            if (((unsigned)sx < Ww) & ((unsigned)sy < Hh)) {
                float dx = fx + cxo0;
                float dy = fy + cyo0;
                float w = __fdividef(1.0f, fmaf(dx, dx, fmaf(dy, dy, EPSF)));
                int idx = base + ioff0;
                red_add_v4(&g_acc4[idx], w * s0, w * s1, w * s2, w * sw);
                red_add_f32(&out_weight[idx], w);
            }
        }
        if (has1) {
            int sx = pxb + ox1, sy = pyb + oy1;
            if (((unsigned)sx < Ww) & ((unsigned)sy < Hh)) {
                float dx = fx + cxo1;
                float dy = fy + cyo1;
                float w = __fdividef(1.0f, fmaf(dx, dx, fmaf(dy, dy, EPSF)));
                int idx = base + ioff1;
                red_add_v4(&g_acc4[idx], w * s0, w * s1, w * s2, w * sw);
                red_add_f32(&out_weight[idx], w);
            }
        }
    }
}

// ---- k4: acc4 -> color/imw with smem-staged coalesced color stores;
//          pure-store depth-key reset (no load) ----
__global__ void __launch_bounds__(256) k_final(float* __restrict__ out_color,
                                               float* __restrict__ out_imw) {
    __shared__ float sc[256 * 3];
    int i = blockIdx.x * 256 + threadIdx.x;   // HW % 256 == 0, no bounds check
    float4 a = g_acc4[i];
    sc[threadIdx.x * 3 + 0] = a.x;            // stride-3 smem: conflict-free (gcd(3,32)=1)
    sc[threadIdx.x * 3 + 1] = a.y;
    sc[threadIdx.x * 3 + 2] = a.z;
    out_imw[i] = a.w;
    g_depth_key[i] = 0u;                       // reset invariant for next replay
    __syncthreads();
    float4* oc = reinterpret_cast<float4*>(out_color) + blockIdx.x * 192;
    if (threadIdx.x < 192)
        oc[threadIdx.x] = reinterpret_cast<const float4*>(sc)[threadIdx.x];
}

extern "C" void kernel_launch(void* const* d_in, const int* in_sizes, int n_in,
                              void* d_out, int out_size) {
    const float* pts    = (const float*)d_in[0];
    const float* color  = (const float*)d_in[1];
    const float* imw    = (const float*)d_in[2];
    const int*   mask   = (const int*)  d_in[3];
    const float* thresh = (const float*)d_in[4];
    int n = in_sizes[3];

    float* out = (float*)d_out;
    float* out_depth  = out;
    float* out_color  = out + HW;
    float* out_imw    = out + HW * 4;
    float* out_weight = out + HW * 5;
    float* out_vis    = out + HW * 6;

    const int BT = 256;
    int gp  = (n + BT - 1) / BT;          // 782
    int gf  = HW / BT;                    // 1440
    int gt  = (Ww / TW) * (Hh / TH);      // 1440

    k_zmin<<<gp, BT>>>(pts, mask, n);
    k_patchmin<<<gt, BT>>>(out_weight, out_depth);
    k_splat<<<gp, BT>>>(pts, color, imw, mask, thresh, out_weight, out_vis, n);
    k_final<<<gf, BT>>>(out_color, out_imw);
}